// round 4
// baseline (speedup 1.0000x reference)
#include <cuda_runtime.h>
#include <cstdint>

// Problem constants
#define BATCH 4096
#define DIM   4096
// layer structure: 16 blocks of 256 (DIV = [16,16])
#define NBLK  16
#define SEC   256

// ---------------------------------------------------------------------------
// Scratch (static device globals; no runtime allocation allowed)
// ---------------------------------------------------------------------------
__device__ float g_h1[BATCH * DIM];       // 64 MB, layer1 output (post-ReLU)
__device__ float g_h2[BATCH * DIM];       // 64 MB, layer2 output (post-ReLU)
__device__ float g_w2ct[NBLK * DIM];      // compact W2, k-major: [k][j]
__device__ float g_w3ct[NBLK * DIM];      // compact W3, k-major: [k][o]

// ---------------------------------------------------------------------------
// Pack kernel: extract the <=16 structurally-nonzero weights per output row.
//   m2[j, k*256 + (j&255)] = 1 for k <= j>>8   (zero-pad the rest)
//   m3[o, k*256 + (o&255)] = 1 for k = 0..15
// Stored k-major so the sparse kernels read 64-float contiguous runs.
// ---------------------------------------------------------------------------
__global__ void pack_kernel(const float* __restrict__ W2,
                            const float* __restrict__ W3)
{
    int idx = blockIdx.x * 256 + threadIdx.x;      // 0 .. 16*4096-1
    if (idx >= NBLK * DIM) return;
    int k = idx >> 12;          // 0..15
    int o = idx & (DIM - 1);    // 0..4095
    int c = o & (SEC - 1);
    float v2 = (k <= (o >> 8)) ? W2[o * DIM + k * SEC + c] : 0.0f;
    g_w2ct[idx] = v2;
    g_w3ct[idx] = W3[o * DIM + k * SEC + c];
}

// ---------------------------------------------------------------------------
// Layer 1: 16 independent dense GEMMs, M=4096 (batch), N=256, K=256 per block.
//   h1[b, o] = relu( b1[o] + sum_k x[b, base+k] * W1[o, base+k] ),
//   base = (o>>8)*256.
// Classic fp32 SGEMM: 128x128 CTA tile, 8x8 per thread, BK=16.
// grid = (4096/128, 256/128, 16) = (32, 2, 16); block = 256 threads.
// ---------------------------------------------------------------------------
__global__ void __launch_bounds__(256) layer1_kernel(
    const float* __restrict__ X,    // [4096, 4096]
    const float* __restrict__ W1,   // [4096, 4096]
    const float* __restrict__ b1)   // [4096]
{
    const int g    = blockIdx.z;
    const int m0   = blockIdx.x * 128;
    const int n0   = blockIdx.y * 128;      // within this block's 256 rows
    const int base = g * SEC;

    __shared__ float As[16][128];
    __shared__ float Bs[16][128];

    const int tid = threadIdx.x;
    const int tx  = tid & 15;   // n dimension (8 cols each)
    const int ty  = tid >> 4;   // m dimension (8 rows each)

    float acc[8][8];
#pragma unroll
    for (int i = 0; i < 8; i++)
#pragma unroll
        for (int j = 0; j < 8; j++) acc[i][j] = 0.0f;

    for (int k0 = 0; k0 < SEC; k0 += 16) {
        // Load A tile (128 x 16) transposed into As[k][m], float4 per thread x2
#pragma unroll
        for (int l = 0; l < 2; l++) {
            int p   = tid + 256 * l;
            int row = p >> 2;
            int kq  = (p & 3) * 4;
            float4 v = *reinterpret_cast<const float4*>(
                &X[(m0 + row) * DIM + base + k0 + kq]);
            As[kq + 0][row] = v.x;
            As[kq + 1][row] = v.y;
            As[kq + 2][row] = v.z;
            As[kq + 3][row] = v.w;
        }
        // Load B tile (128 x 16) transposed into Bs[k][n]
#pragma unroll
        for (int l = 0; l < 2; l++) {
            int p   = tid + 256 * l;
            int row = p >> 2;
            int kq  = (p & 3) * 4;
            float4 v = *reinterpret_cast<const float4*>(
                &W1[(base + n0 + row) * DIM + base + k0 + kq]);
            Bs[kq + 0][row] = v.x;
            Bs[kq + 1][row] = v.y;
            Bs[kq + 2][row] = v.z;
            Bs[kq + 3][row] = v.w;
        }
        __syncthreads();

#pragma unroll
        for (int kk = 0; kk < 16; kk++) {
            float a[8], bb[8];
#pragma unroll
            for (int i = 0; i < 8; i++) a[i]  = As[kk][ty * 8 + i];
#pragma unroll
            for (int j = 0; j < 8; j++) bb[j] = Bs[kk][tx * 8 + j];
#pragma unroll
            for (int i = 0; i < 8; i++)
#pragma unroll
                for (int j = 0; j < 8; j++)
                    acc[i][j] = fmaf(a[i], bb[j], acc[i][j]);
        }
        __syncthreads();
    }

    // Epilogue: bias + ReLU, vectorized store
    const int ob = base + n0 + tx * 8;   // global output column
    float bias[8];
#pragma unroll
    for (int j = 0; j < 8; j++) bias[j] = b1[ob + j];

#pragma unroll
    for (int i = 0; i < 8; i++) {
        int m = m0 + ty * 8 + i;
        float4 v0, v1;
        v0.x = fmaxf(acc[i][0] + bias[0], 0.0f);
        v0.y = fmaxf(acc[i][1] + bias[1], 0.0f);
        v0.z = fmaxf(acc[i][2] + bias[2], 0.0f);
        v0.w = fmaxf(acc[i][3] + bias[3], 0.0f);
        v1.x = fmaxf(acc[i][4] + bias[4], 0.0f);
        v1.y = fmaxf(acc[i][5] + bias[5], 0.0f);
        v1.z = fmaxf(acc[i][6] + bias[6], 0.0f);
        v1.w = fmaxf(acc[i][7] + bias[7], 0.0f);
        *reinterpret_cast<float4*>(&g_h1[m * DIM + ob])     = v0;
        *reinterpret_cast<float4*>(&g_h1[m * DIM + ob + 4]) = v1;
    }
}

// ---------------------------------------------------------------------------
// Sparse-16 layer: out[b, o] = (relu)( bias[o] + sum_{k=0..15}
//                                       Wct[k][o] * in[b, k*256 + (o&255)] )
// Block: 256 threads, handles a 64-wide c-chunk (cx = blockIdx.x in 0..3)
// for ALL 16 o-blocks, looping over a chunk of batch rows.
//   thread: c = tid&63, owns 4 o-blocks (oy0 = (tid>>6)*4) -> 64 weights in
//   registers (loaded once per block), activations staged per-b in 4 KB smem.
// ---------------------------------------------------------------------------
#define BCNT 16   // batch rows per block; grid.y = 4096/BCNT = 256

template <bool RELU>
__device__ __forceinline__ void sparse16_body(
    const float* __restrict__ in,
    const float* __restrict__ Wct,
    const float* __restrict__ bias,
    float* __restrict__ out)
{
    const int cx   = blockIdx.x;              // 0..3
    const int tid  = threadIdx.x;
    const int c    = tid & 63;
    const int oy0  = (tid >> 6) * 4;          // 0,4,8,12
    const int ccol = cx * 64 + c;              // 0..255

    __shared__ float in_s[NBLK * 64];

    // Weights + bias in registers (read once per block from L2)
    float w[4][NBLK];
    float bv[4];
#pragma unroll
    for (int u = 0; u < 4; u++) {
        int o = (oy0 + u) * SEC + ccol;
        bv[u] = bias[o];
#pragma unroll
        for (int k = 0; k < NBLK; k++)
            w[u][k] = Wct[k * DIM + o];
    }

    const int bstart = blockIdx.y * BCNT;
    for (int bi = 0; bi < BCNT; bi++) {
        const int b = bstart + bi;
        // Cooperative load of the 16x64 activation slab this block needs
#pragma unroll
        for (int l = 0; l < 4; l++) {
            int idx = tid + 256 * l;
            int k   = idx >> 6;
            int cc  = idx & 63;
            in_s[idx] = in[b * DIM + k * SEC + cx * 64 + cc];
        }
        __syncthreads();

        float iv[NBLK];
#pragma unroll
        for (int k = 0; k < NBLK; k++) iv[k] = in_s[k * 64 + c];

#pragma unroll
        for (int u = 0; u < 4; u++) {
            float acc = bv[u];
#pragma unroll
            for (int k = 0; k < NBLK; k++)
                acc = fmaf(w[u][k], iv[k], acc);
            if (RELU) acc = fmaxf(acc, 0.0f);
            out[b * DIM + (oy0 + u) * SEC + ccol] = acc;
        }
        __syncthreads();
    }
}

__global__ void __launch_bounds__(256) layer2_kernel(const float* __restrict__ b2)
{
    sparse16_body<true>(g_h1, g_w2ct, b2, g_h2);
}

__global__ void __launch_bounds__(256) layer3_kernel(const float* __restrict__ b3,
                                                     float* __restrict__ out)
{
    sparse16_body<false>(g_h2, g_w3ct, b3, out);
}

// ---------------------------------------------------------------------------
// Launch
// Inputs (metadata order): x, W1, b1, W2, b2, W3, b3, m1, m2, m3
// Masks m1/m2/m3 are fixed structural patterns and are decoded analytically.
// ---------------------------------------------------------------------------
extern "C" void kernel_launch(void* const* d_in, const int* in_sizes, int n_in,
                              void* d_out, int out_size)
{
    const float* x  = (const float*)d_in[0];
    const float* W1 = (const float*)d_in[1];
    const float* b1 = (const float*)d_in[2];
    const float* W2 = (const float*)d_in[3];
    const float* b2 = (const float*)d_in[4];
    const float* W3 = (const float*)d_in[5];
    const float* b3 = (const float*)d_in[6];
    float* out = (float*)d_out;
    (void)in_sizes; (void)n_in; (void)out_size;

    // 1) Pack compact sparse weight tables for layers 2 and 3
    pack_kernel<<<(NBLK * DIM + 255) / 256, 256>>>(W2, W3);

    // 2) Layer 1: 16 block-diagonal dense GEMMs, fused bias+ReLU
    layer1_kernel<<<dim3(BATCH / 128, SEC / 128, NBLK), 256>>>(x, W1, b1);

    // 3) Layer 2: 16-tap strided sparse layer, fused bias+ReLU
    layer2_kernel<<<dim3(4, BATCH / BCNT), 256>>>(b2);

    // 4) Layer 3: 16-tap strided sparse layer, fused bias (no activation)
    layer3_kernel<<<dim3(4, BATCH / BCNT), 256>>>(b3, out);
}

// round 5
// speedup vs baseline: 1.1964x; 1.1964x over previous
#include <cuda_runtime.h>
#include <cstdint>

// Problem constants
#define BATCH 4096
#define DIM   4096
#define NBLK  16
#define SEC   256

// ---------------------------------------------------------------------------
// Scratch (static device globals; no runtime allocation allowed)
// ---------------------------------------------------------------------------
__device__ float g_h1[BATCH * DIM];       // 64 MB, layer1 output (post-ReLU)
__device__ float g_w2ct[NBLK * DIM];      // compact W2, k-major: [k][j]
__device__ float g_w3ct[NBLK * DIM];      // compact W3, k-major: [k][o]

// ---------------------------------------------------------------------------
// Pack kernel: extract the <=16 structurally-nonzero weights per output row.
//   m2[j, k*256 + (j&255)] = 1 for k <= j>>8   (zero-pad the rest)
//   m3[o, k*256 + (o&255)] = 1 for k = 0..15
// ---------------------------------------------------------------------------
__global__ void pack_kernel(const float* __restrict__ W2,
                            const float* __restrict__ W3)
{
    int idx = blockIdx.x * 256 + threadIdx.x;      // 0 .. 16*4096-1
    if (idx >= NBLK * DIM) return;
    int k = idx >> 12;          // 0..15
    int o = idx & (DIM - 1);    // 0..4095
    int c = o & (SEC - 1);
    float v2 = (k <= (o >> 8)) ? W2[o * DIM + k * SEC + c] : 0.0f;
    g_w2ct[idx] = v2;
    g_w3ct[idx] = W3[o * DIM + k * SEC + c];
}

// ---------------------------------------------------------------------------
// Layer 1: 16 independent dense GEMMs (block-diagonal), fused bias+ReLU.
// fp32 SGEMM: 128x128 CTA tile, 8x8 per thread, BK=16. FFMA-bound at peak.
// ---------------------------------------------------------------------------
__global__ void __launch_bounds__(256) layer1_kernel(
    const float* __restrict__ X,    // [4096, 4096]
    const float* __restrict__ W1,   // [4096, 4096]
    const float* __restrict__ b1)   // [4096]
{
    const int g    = blockIdx.z;
    const int m0   = blockIdx.x * 128;
    const int n0   = blockIdx.y * 128;
    const int base = g * SEC;

    __shared__ float As[16][128];
    __shared__ float Bs[16][128];

    const int tid = threadIdx.x;
    const int tx  = tid & 15;
    const int ty  = tid >> 4;

    float acc[8][8];
#pragma unroll
    for (int i = 0; i < 8; i++)
#pragma unroll
        for (int j = 0; j < 8; j++) acc[i][j] = 0.0f;

    for (int k0 = 0; k0 < SEC; k0 += 16) {
#pragma unroll
        for (int l = 0; l < 2; l++) {
            int p   = tid + 256 * l;
            int row = p >> 2;
            int kq  = (p & 3) * 4;
            float4 v = *reinterpret_cast<const float4*>(
                &X[(m0 + row) * DIM + base + k0 + kq]);
            As[kq + 0][row] = v.x;
            As[kq + 1][row] = v.y;
            As[kq + 2][row] = v.z;
            As[kq + 3][row] = v.w;
        }
#pragma unroll
        for (int l = 0; l < 2; l++) {
            int p   = tid + 256 * l;
            int row = p >> 2;
            int kq  = (p & 3) * 4;
            float4 v = *reinterpret_cast<const float4*>(
                &W1[(base + n0 + row) * DIM + base + k0 + kq]);
            Bs[kq + 0][row] = v.x;
            Bs[kq + 1][row] = v.y;
            Bs[kq + 2][row] = v.z;
            Bs[kq + 3][row] = v.w;
        }
        __syncthreads();

#pragma unroll
        for (int kk = 0; kk < 16; kk++) {
            float a[8], bb[8];
#pragma unroll
            for (int i = 0; i < 8; i++) a[i]  = As[kk][ty * 8 + i];
#pragma unroll
            for (int j = 0; j < 8; j++) bb[j] = Bs[kk][tx * 8 + j];
#pragma unroll
            for (int i = 0; i < 8; i++)
#pragma unroll
                for (int j = 0; j < 8; j++)
                    acc[i][j] = fmaf(a[i], bb[j], acc[i][j]);
        }
        __syncthreads();
    }

    const int ob = base + n0 + tx * 8;
    float bias[8];
#pragma unroll
    for (int j = 0; j < 8; j++) bias[j] = b1[ob + j];

#pragma unroll
    for (int i = 0; i < 8; i++) {
        int m = m0 + ty * 8 + i;
        float4 v0, v1;
        v0.x = fmaxf(acc[i][0] + bias[0], 0.0f);
        v0.y = fmaxf(acc[i][1] + bias[1], 0.0f);
        v0.z = fmaxf(acc[i][2] + bias[2], 0.0f);
        v0.w = fmaxf(acc[i][3] + bias[3], 0.0f);
        v1.x = fmaxf(acc[i][4] + bias[4], 0.0f);
        v1.y = fmaxf(acc[i][5] + bias[5], 0.0f);
        v1.z = fmaxf(acc[i][6] + bias[6], 0.0f);
        v1.w = fmaxf(acc[i][7] + bias[7], 0.0f);
        *reinterpret_cast<float4*>(&g_h1[m * DIM + ob])     = v0;
        *reinterpret_cast<float4*>(&g_h1[m * DIM + ob + 4]) = v1;
    }
}

// ---------------------------------------------------------------------------
// FUSED layers 2+3. For fixed c (= column within a 256-wide section):
//   h2[b, oy*256+c]  = relu(b2 + sum_{k<=oy} w2ct[k][oy*256+c] * h1[b, k*256+c])
//   out[b, o3*256+c] =      b3 + sum_{k}     w3ct[k][o3*256+c] * h2[b, k*256+c]
// h2 lives only in shared memory -> saves 128 MB of DRAM traffic.
//
// Block: 512 threads = 64 c-columns x 8 groups; each group owns 2 o-blocks.
// Per thread: 2x16 w2 + 2x16 w3 weights in registers (loaded once).
// Stages R=4 batch rows per barrier for latency hiding.
// Grid: (4 c-chunks, 4096/BCNT batch chunks).
// ---------------------------------------------------------------------------
#define FB_R    4
#define FB_BCNT 16

__global__ void __launch_bounds__(512) fused23_kernel(
    const float* __restrict__ b2,
    const float* __restrict__ b3,
    float* __restrict__ out)
{
    const int cx   = blockIdx.x;            // 0..3
    const int tid  = threadIdx.x;
    const int c    = tid & 63;
    const int gq   = tid >> 6;               // 0..7
    const int ccol = cx * 64 + c;             // 0..255

    __shared__ float h1s[FB_R][NBLK * 64];    // 16 KB
    __shared__ float h2s[FB_R][NBLK * 64];    // 16 KB

    // Weights + biases in registers (read once per block from L2)
    float w2[2][NBLK], w3[2][NBLK], bv2[2], bv3[2];
#pragma unroll
    for (int u = 0; u < 2; u++) {
        int oy = gq * 2 + u;
        int o  = oy * SEC + ccol;
        bv2[u] = b2[o];
        bv3[u] = b3[o];
#pragma unroll
        for (int k = 0; k < NBLK; k++) {
            w2[u][k] = g_w2ct[k * DIM + o];
            w3[u][k] = g_w3ct[k * DIM + o];
        }
    }

    const int b0 = blockIdx.y * FB_BCNT;

    for (int s = 0; s < FB_BCNT; s += FB_R) {
        // ---- Stage-load FB_R rows of the 16x64 h1 slab (float4, coalesced)
#pragma unroll
        for (int l = 0; l < 2; l++) {
            int t  = tid + 512 * l;           // 0..1023 -> 1024 float4s
            int r  = t >> 8;
            int q  = t & 255;
            int k  = q >> 4;
            int cc = (q & 15) * 4;
            float4 v = *reinterpret_cast<const float4*>(
                &g_h1[(size_t)(b0 + s + r) * DIM + k * SEC + cx * 64 + cc]);
            *reinterpret_cast<float4*>(&h1s[r][k * 64 + cc]) = v;
        }
        __syncthreads();

        // ---- Layer 2: each thread produces 2 h2 values per row
#pragma unroll
        for (int r = 0; r < FB_R; r++) {
            float iv[NBLK];
#pragma unroll
            for (int k = 0; k < NBLK; k++) iv[k] = h1s[r][k * 64 + c];
#pragma unroll
            for (int u = 0; u < 2; u++) {
                float acc = bv2[u];
#pragma unroll
                for (int k = 0; k < NBLK; k++)
                    acc = fmaf(w2[u][k], iv[k], acc);
                h2s[r][(gq * 2 + u) * 64 + c] = fmaxf(acc, 0.0f);
            }
        }
        __syncthreads();

        // ---- Layer 3: each thread produces 2 outputs per row
#pragma unroll
        for (int r = 0; r < FB_R; r++) {
            float hv[NBLK];
#pragma unroll
            for (int k = 0; k < NBLK; k++) hv[k] = h2s[r][k * 64 + c];
#pragma unroll
            for (int u = 0; u < 2; u++) {
                float acc = bv3[u];
#pragma unroll
                for (int k = 0; k < NBLK; k++)
                    acc = fmaf(w3[u][k], hv[k], acc);
                out[(size_t)(b0 + s + r) * DIM + (gq * 2 + u) * SEC + ccol] = acc;
            }
        }
        __syncthreads();
    }
}

// ---------------------------------------------------------------------------
// Launch. Inputs (metadata order): x, W1, b1, W2, b2, W3, b3, m1, m2, m3
// Masks are fixed structural patterns, decoded analytically.
// ---------------------------------------------------------------------------
extern "C" void kernel_launch(void* const* d_in, const int* in_sizes, int n_in,
                              void* d_out, int out_size)
{
    const float* x  = (const float*)d_in[0];
    const float* W1 = (const float*)d_in[1];
    const float* b1 = (const float*)d_in[2];
    const float* W2 = (const float*)d_in[3];
    const float* b2 = (const float*)d_in[4];
    const float* W3 = (const float*)d_in[5];
    const float* b3 = (const float*)d_in[6];
    float* out = (float*)d_out;
    (void)in_sizes; (void)n_in; (void)out_size;

    // 1) Pack compact sparse weight tables for layers 2 and 3
    pack_kernel<<<(NBLK * DIM + 255) / 256, 256>>>(W2, W3);

    // 2) Layer 1: 16 block-diagonal dense GEMMs, fused bias+ReLU
    layer1_kernel<<<dim3(BATCH / 128, SEC / 128, NBLK), 256>>>(x, W1, b1);

    // 3) Layers 2+3 fused: h2 never touches DRAM
    fused23_kernel<<<dim3(4, BATCH / FB_BCNT), 512>>>(b2, b3, out);
}

// round 9
// speedup vs baseline: 1.9493x; 1.6293x over previous
#include <cuda_runtime.h>
#include <cuda_bf16.h>
#include <cstdint>

// Problem constants
#define BATCH 4096
#define DIM   4096
#define NBLK  16
#define SEC   256

// ---------------------------------------------------------------------------
// Scratch (static device globals; no runtime allocation allowed)
// ---------------------------------------------------------------------------
__device__ float g_h1[BATCH * DIM];       // 64 MB, layer1 output (post-ReLU)
__device__ float g_w2ct[NBLK * DIM];      // compact W2, k-major
__device__ float g_w3ct[NBLK * DIM];      // compact W3, k-major

__device__ __forceinline__ uint32_t smem_u32(const void* p) {
    uint32_t a;
    asm("{ .reg .u64 t; cvta.to.shared.u64 t, %1; cvt.u32.u64 %0, t; }"
        : "=r"(a) : "l"(p));
    return a;
}

// ---------------------------------------------------------------------------
// Pack kernel: compact sparse weight tables for layers 2/3
//   m2[j, k*256 + (j&255)] = 1 for k <= j>>8 ; m3[o, k*256 + (o&255)] = 1 all k
// ---------------------------------------------------------------------------
__global__ void pack_kernel(const float* __restrict__ W2,
                            const float* __restrict__ W3)
{
    int idx = blockIdx.x * 256 + threadIdx.x;
    if (idx >= NBLK * DIM) return;
    int k = idx >> 12;
    int o = idx & (DIM - 1);
    int c = o & (SEC - 1);
    float v2 = (k <= (o >> 8)) ? W2[o * DIM + k * SEC + c] : 0.0f;
    g_w2ct[idx] = v2;
    g_w3ct[idx] = W3[o * DIM + k * SEC + c];
}

// ---------------------------------------------------------------------------
// Layer 1 on tensor cores via mma.sync bf16 (bf16x3 split => ~fp32 accuracy).
// 16 block-diagonal GEMMs: per group, C[4096,256] = X[:,sec] @ W1[sec,sec]^T.
// CTA tile 128x128, BK=32; 8 warps (4 m x 2 n), warp tile 32x64.
// ---------------------------------------------------------------------------
#define LDS 40   // padded smem row stride (elements); 80B rows, conflict-free

__device__ __forceinline__ void ldmatrix_x4(
    uint32_t& r0, uint32_t& r1, uint32_t& r2, uint32_t& r3, uint32_t addr)
{
    asm volatile("ldmatrix.sync.aligned.m8n8.x4.shared.b16 {%0,%1,%2,%3}, [%4];"
                 : "=r"(r0), "=r"(r1), "=r"(r2), "=r"(r3) : "r"(addr));
}
__device__ __forceinline__ void mma_bf16(
    float* c, uint32_t a0, uint32_t a1, uint32_t a2, uint32_t a3,
    uint32_t b0, uint32_t b1)
{
    asm volatile(
        "mma.sync.aligned.m16n8k16.row.col.f32.bf16.bf16.f32 "
        "{%0,%1,%2,%3}, {%4,%5,%6,%7}, {%8,%9}, {%0,%1,%2,%3};"
        : "+f"(c[0]), "+f"(c[1]), "+f"(c[2]), "+f"(c[3])
        : "r"(a0), "r"(a1), "r"(a2), "r"(a3), "r"(b0), "r"(b1));
}

// split one float4 into packed bf16x2 hi / lo pairs (memory order [e0,e1])
__device__ __forceinline__ void split4(const float4 v, uint2& hi, uint2& lo)
{
    __nv_bfloat162 h01, h23, l01, l23;
    h01.x = __float2bfloat16(v.x);  h01.y = __float2bfloat16(v.y);
    h23.x = __float2bfloat16(v.z);  h23.y = __float2bfloat16(v.w);
    l01.x = __float2bfloat16(v.x - __bfloat162float(h01.x));
    l01.y = __float2bfloat16(v.y - __bfloat162float(h01.y));
    l23.x = __float2bfloat16(v.z - __bfloat162float(h23.x));
    l23.y = __float2bfloat16(v.w - __bfloat162float(h23.y));
    hi.x = *reinterpret_cast<uint32_t*>(&h01);
    hi.y = *reinterpret_cast<uint32_t*>(&h23);
    lo.x = *reinterpret_cast<uint32_t*>(&l01);
    lo.y = *reinterpret_cast<uint32_t*>(&l23);
}

__global__ void __launch_bounds__(256, 2) layer1_mma_kernel(
    const float* __restrict__ X,
    const float* __restrict__ W1,
    const float* __restrict__ b1)
{
    __shared__ __align__(16) __nv_bfloat16 sA_hi[128 * LDS];
    __shared__ __align__(16) __nv_bfloat16 sA_lo[128 * LDS];
    __shared__ __align__(16) __nv_bfloat16 sB_hi[128 * LDS];
    __shared__ __align__(16) __nv_bfloat16 sB_lo[128 * LDS];

    const int tid    = threadIdx.x;
    const int lane   = tid & 31;
    const int wid    = tid >> 5;
    const int wm0    = (wid & 3) * 32;     // warp row base within CTA tile
    const int wn0    = (wid >> 2) * 64;    // warp col base within CTA tile
    const int m0     = blockIdx.x * 128;   // batch rows
    const int n0     = blockIdx.y * 128;   // out cols within section
    const int base   = blockIdx.z * SEC;   // section base

    float acc[2][8][4];
#pragma unroll
    for (int mi = 0; mi < 2; mi++)
#pragma unroll
        for (int ni = 0; ni < 8; ni++)
#pragma unroll
            for (int q = 0; q < 4; q++) acc[mi][ni][q] = 0.0f;

    // per-thread global load coords: 128 rows x 8 float4 per tile, 4 each
    const int lrow = tid >> 1;             // shared by pairs
    // simpler: idx-based inside loop

    for (int ch = 0; ch < SEC / 32; ch++) {
        const int k0 = ch * 32;

        // ---- Prefetch global (before barrier: overlaps previous MMAs)
        float4 av[4], bv[4];
#pragma unroll
        for (int i = 0; i < 4; i++) {
            int idx = tid + 256 * i;        // 0..1023
            int row = idx >> 3;
            int f4  = idx & 7;
            av[i] = *reinterpret_cast<const float4*>(
                &X[(size_t)(m0 + row) * DIM + base + k0 + f4 * 4]);
            bv[i] = *reinterpret_cast<const float4*>(
                &W1[(size_t)(base + n0 + row) * DIM + base + k0 + f4 * 4]);
        }

        if (ch) __syncthreads();            // smem safe to overwrite

        // ---- Split + store to smem
#pragma unroll
        for (int i = 0; i < 4; i++) {
            int idx = tid + 256 * i;
            int row = idx >> 3;
            int f4  = idx & 7;
            int off = row * LDS + f4 * 4;
            uint2 hi, lo;
            split4(av[i], hi, lo);
            *reinterpret_cast<uint2*>(&sA_hi[off]) = hi;
            *reinterpret_cast<uint2*>(&sA_lo[off]) = lo;
            split4(bv[i], hi, lo);
            *reinterpret_cast<uint2*>(&sB_hi[off]) = hi;
            *reinterpret_cast<uint2*>(&sB_lo[off]) = lo;
        }
        __syncthreads();

        // ---- 3 passes: hi*hi, lo*hi, hi*lo
#pragma unroll
        for (int pass = 0; pass < 3; pass++) {
            const __nv_bfloat16* Ap = (pass == 1) ? sA_lo : sA_hi;
            const __nv_bfloat16* Bp = (pass == 2) ? sB_lo : sB_hi;
#pragma unroll
            for (int ks = 0; ks < 2; ks++) {
                uint32_t a[2][4];
#pragma unroll
                for (int mi = 0; mi < 2; mi++) {
                    uint32_t addr = smem_u32(
                        &Ap[(wm0 + mi * 16 + (lane & 15)) * LDS +
                            ks * 16 + (lane >> 4) * 8]);
                    ldmatrix_x4(a[mi][0], a[mi][1], a[mi][2], a[mi][3], addr);
                }
                uint32_t b[4][4];
#pragma unroll
                for (int np = 0; np < 4; np++) {
                    uint32_t addr = smem_u32(
                        &Bp[(wn0 + np * 16 + ((lane >> 4) << 3) + (lane & 7)) * LDS +
                            ks * 16 + (((lane >> 3) & 1) << 3)]);
                    ldmatrix_x4(b[np][0], b[np][1], b[np][2], b[np][3], addr);
                }
#pragma unroll
                for (int mi = 0; mi < 2; mi++)
#pragma unroll
                    for (int ni = 0; ni < 8; ni++) {
                        int np = ni >> 1, h = (ni & 1) * 2;
                        mma_bf16(acc[mi][ni],
                                 a[mi][0], a[mi][1], a[mi][2], a[mi][3],
                                 b[np][h], b[np][h + 1]);
                    }
            }
        }
    }

    // ---- Epilogue: bias + ReLU, float2 stores
    const int g = lane >> 2;
    const int c = lane & 3;
#pragma unroll
    for (int mi = 0; mi < 2; mi++) {
        const int row0 = m0 + wm0 + mi * 16 + g;
        const int row1 = row0 + 8;
#pragma unroll
        for (int ni = 0; ni < 8; ni++) {
            const int col = base + n0 + wn0 + ni * 8 + 2 * c;
            const float bb0 = b1[col], bb1 = b1[col + 1];
            float2 v0, v1;
            v0.x = fmaxf(acc[mi][ni][0] + bb0, 0.0f);
            v0.y = fmaxf(acc[mi][ni][1] + bb1, 0.0f);
            v1.x = fmaxf(acc[mi][ni][2] + bb0, 0.0f);
            v1.y = fmaxf(acc[mi][ni][3] + bb1, 0.0f);
            *reinterpret_cast<float2*>(&g_h1[(size_t)row0 * DIM + col]) = v0;
            *reinterpret_cast<float2*>(&g_h1[(size_t)row1 * DIM + col]) = v1;
        }
    }
}

// ---------------------------------------------------------------------------
// FUSED layers 2+3 (unchanged): h2 lives only in shared memory.
// ---------------------------------------------------------------------------
#define FB_R    4
#define FB_BCNT 16

__global__ void __launch_bounds__(512) fused23_kernel(
    const float* __restrict__ b2,
    const float* __restrict__ b3,
    float* __restrict__ out)
{
    const int cx   = blockIdx.x;
    const int tid  = threadIdx.x;
    const int c    = tid & 63;
    const int gq   = tid >> 6;
    const int ccol = cx * 64 + c;

    __shared__ float h1s[FB_R][NBLK * 64];
    __shared__ float h2s[FB_R][NBLK * 64];

    float w2[2][NBLK], w3[2][NBLK], bv2[2], bv3[2];
#pragma unroll
    for (int u = 0; u < 2; u++) {
        int oy = gq * 2 + u;
        int o  = oy * SEC + ccol;
        bv2[u] = b2[o];
        bv3[u] = b3[o];
#pragma unroll
        for (int k = 0; k < NBLK; k++) {
            w2[u][k] = g_w2ct[k * DIM + o];
            w3[u][k] = g_w3ct[k * DIM + o];
        }
    }

    const int b0 = blockIdx.y * FB_BCNT;

    for (int s = 0; s < FB_BCNT; s += FB_R) {
#pragma unroll
        for (int l = 0; l < 2; l++) {
            int t  = tid + 512 * l;
            int r  = t >> 8;
            int q  = t & 255;
            int k  = q >> 4;
            int cc = (q & 15) * 4;
            float4 v = *reinterpret_cast<const float4*>(
                &g_h1[(size_t)(b0 + s + r) * DIM + k * SEC + cx * 64 + cc]);
            *reinterpret_cast<float4*>(&h1s[r][k * 64 + cc]) = v;
        }
        __syncthreads();

#pragma unroll
        for (int r = 0; r < FB_R; r++) {
            float iv[NBLK];
#pragma unroll
            for (int k = 0; k < NBLK; k++) iv[k] = h1s[r][k * 64 + c];
#pragma unroll
            for (int u = 0; u < 2; u++) {
                float acc = bv2[u];
#pragma unroll
                for (int k = 0; k < NBLK; k++)
                    acc = fmaf(w2[u][k], iv[k], acc);
                h2s[r][(gq * 2 + u) * 64 + c] = fmaxf(acc, 0.0f);
            }
        }
        __syncthreads();

#pragma unroll
        for (int r = 0; r < FB_R; r++) {
            float hv[NBLK];
#pragma unroll
            for (int k = 0; k < NBLK; k++) hv[k] = h2s[r][k * 64 + c];
#pragma unroll
            for (int u = 0; u < 2; u++) {
                float acc = bv3[u];
#pragma unroll
                for (int k = 0; k < NBLK; k++)
                    acc = fmaf(w3[u][k], hv[k], acc);
                out[(size_t)(b0 + s + r) * DIM + (gq * 2 + u) * SEC + ccol] = acc;
            }
        }
        __syncthreads();
    }
}

// ---------------------------------------------------------------------------
// Launch. Inputs (metadata order): x, W1, b1, W2, b2, W3, b3, m1, m2, m3
// ---------------------------------------------------------------------------
extern "C" void kernel_launch(void* const* d_in, const int* in_sizes, int n_in,
                              void* d_out, int out_size)
{
    const float* x  = (const float*)d_in[0];
    const float* W1 = (const float*)d_in[1];
    const float* b1 = (const float*)d_in[2];
    const float* W2 = (const float*)d_in[3];
    const float* b2 = (const float*)d_in[4];
    const float* W3 = (const float*)d_in[5];
    const float* b3 = (const float*)d_in[6];
    float* out = (float*)d_out;
    (void)in_sizes; (void)n_in; (void)out_size;

    // 1) Pack compact sparse weight tables
    pack_kernel<<<(NBLK * DIM + 255) / 256, 256>>>(W2, W3);

    // 2) Layer 1 on tensor cores (mma.sync bf16, bf16x3 split)
    layer1_mma_kernel<<<dim3(BATCH / 128, 2, NBLK), 256>>>(x, W1, b1);

    // 3) Layers 2+3 fused
    fused23_kernel<<<dim3(4, BATCH / FB_BCNT), 512>>>(b2, b3, out);
}

// round 10
// speedup vs baseline: 1.9520x; 1.0014x over previous
#include <cuda_runtime.h>
#include <cuda_bf16.h>
#include <cstdint>

// Problem constants
#define BATCH 4096
#define DIM   4096
#define NBLK  16
#define SEC   256

// ---------------------------------------------------------------------------
// Scratch (static device globals; no runtime allocation allowed)
// ---------------------------------------------------------------------------
__device__ float g_h1[BATCH * DIM];       // 64 MB, layer1 output (post-ReLU)
__device__ float g_w2ct[NBLK * DIM];      // compact W2, k-major
__device__ float g_w3ct[NBLK * DIM];      // compact W3, k-major

__device__ __forceinline__ uint32_t smem_u32(const void* p) {
    uint32_t a;
    asm("{ .reg .u64 t; cvta.to.shared.u64 t, %1; cvt.u32.u64 %0, t; }"
        : "=r"(a) : "l"(p));
    return a;
}

// ---------------------------------------------------------------------------
// Pack kernel: compact sparse weight tables for layers 2/3
//   m2[j, k*256 + (j&255)] = 1 for k <= j>>8 ; m3[o, k*256 + (o&255)] = 1 all k
// ---------------------------------------------------------------------------
__global__ void pack_kernel(const float* __restrict__ W2,
                            const float* __restrict__ W3)
{
    int idx = blockIdx.x * 256 + threadIdx.x;
    if (idx >= NBLK * DIM) return;
    int k = idx >> 12;
    int o = idx & (DIM - 1);
    int c = o & (SEC - 1);
    float v2 = (k <= (o >> 8)) ? W2[o * DIM + k * SEC + c] : 0.0f;
    g_w2ct[idx] = v2;
    g_w3ct[idx] = W3[o * DIM + k * SEC + c];
}

// ---------------------------------------------------------------------------
// Layer 1 on tensor cores via mma.sync bf16 (bf16x3 split => ~fp32 accuracy).
// 16 block-diagonal GEMMs: per group, C[4096,256] = X[:,sec] @ W1[sec,sec]^T.
// CTA tile 128x128, BK=32; 8 warps (4 m x 2 n), warp tile 32x64.
// ---------------------------------------------------------------------------
#define LDS 40   // padded smem row stride (elements); 80B rows, conflict-free

__device__ __forceinline__ void ldmatrix_x4(
    uint32_t& r0, uint32_t& r1, uint32_t& r2, uint32_t& r3, uint32_t addr)
{
    asm volatile("ldmatrix.sync.aligned.m8n8.x4.shared.b16 {%0,%1,%2,%3}, [%4];"
                 : "=r"(r0), "=r"(r1), "=r"(r2), "=r"(r3) : "r"(addr));
}
__device__ __forceinline__ void mma_bf16(
    float* c, uint32_t a0, uint32_t a1, uint32_t a2, uint32_t a3,
    uint32_t b0, uint32_t b1)
{
    asm volatile(
        "mma.sync.aligned.m16n8k16.row.col.f32.bf16.bf16.f32 "
        "{%0,%1,%2,%3}, {%4,%5,%6,%7}, {%8,%9}, {%0,%1,%2,%3};"
        : "+f"(c[0]), "+f"(c[1]), "+f"(c[2]), "+f"(c[3])
        : "r"(a0), "r"(a1), "r"(a2), "r"(a3), "r"(b0), "r"(b1));
}

// split one float4 into packed bf16x2 hi / lo pairs (memory order [e0,e1])
__device__ __forceinline__ void split4(const float4 v, uint2& hi, uint2& lo)
{
    __nv_bfloat162 h01, h23, l01, l23;
    h01.x = __float2bfloat16(v.x);  h01.y = __float2bfloat16(v.y);
    h23.x = __float2bfloat16(v.z);  h23.y = __float2bfloat16(v.w);
    l01.x = __float2bfloat16(v.x - __bfloat162float(h01.x));
    l01.y = __float2bfloat16(v.y - __bfloat162float(h01.y));
    l23.x = __float2bfloat16(v.z - __bfloat162float(h23.x));
    l23.y = __float2bfloat16(v.w - __bfloat162float(h23.y));
    hi.x = *reinterpret_cast<uint32_t*>(&h01);
    hi.y = *reinterpret_cast<uint32_t*>(&h23);
    lo.x = *reinterpret_cast<uint32_t*>(&l01);
    lo.y = *reinterpret_cast<uint32_t*>(&l23);
}

__global__ void __launch_bounds__(256, 2) layer1_mma_kernel(
    const float* __restrict__ X,
    const float* __restrict__ W1,
    const float* __restrict__ b1)
{
    __shared__ __align__(16) __nv_bfloat16 sA_hi[128 * LDS];
    __shared__ __align__(16) __nv_bfloat16 sA_lo[128 * LDS];
    __shared__ __align__(16) __nv_bfloat16 sB_hi[128 * LDS];
    __shared__ __align__(16) __nv_bfloat16 sB_lo[128 * LDS];

    const int tid    = threadIdx.x;
    const int lane   = tid & 31;
    const int wid    = tid >> 5;
    const int wm0    = (wid & 3) * 32;     // warp row base within CTA tile
    const int wn0    = (wid >> 2) * 64;    // warp col base within CTA tile
    const int m0     = blockIdx.x * 128;   // batch rows
    const int n0     = blockIdx.y * 128;   // out cols within section
    const int base   = blockIdx.z * SEC;   // section base

    float acc[2][8][4];
#pragma unroll
    for (int mi = 0; mi < 2; mi++)
#pragma unroll
        for (int ni = 0; ni < 8; ni++)
#pragma unroll
            for (int q = 0; q < 4; q++) acc[mi][ni][q] = 0.0f;

    // per-thread global load coords: 128 rows x 8 float4 per tile, 4 each
    const int lrow = tid >> 1;             // shared by pairs
    // simpler: idx-based inside loop

    for (int ch = 0; ch < SEC / 32; ch++) {
        const int k0 = ch * 32;

        // ---- Prefetch global (before barrier: overlaps previous MMAs)
        float4 av[4], bv[4];
#pragma unroll
        for (int i = 0; i < 4; i++) {
            int idx = tid + 256 * i;        // 0..1023
            int row = idx >> 3;
            int f4  = idx & 7;
            av[i] = *reinterpret_cast<const float4*>(
                &X[(size_t)(m0 + row) * DIM + base + k0 + f4 * 4]);
            bv[i] = *reinterpret_cast<const float4*>(
                &W1[(size_t)(base + n0 + row) * DIM + base + k0 + f4 * 4]);
        }

        if (ch) __syncthreads();            // smem safe to overwrite

        // ---- Split + store to smem
#pragma unroll
        for (int i = 0; i < 4; i++) {
            int idx = tid + 256 * i;
            int row = idx >> 3;
            int f4  = idx & 7;
            int off = row * LDS + f4 * 4;
            uint2 hi, lo;
            split4(av[i], hi, lo);
            *reinterpret_cast<uint2*>(&sA_hi[off]) = hi;
            *reinterpret_cast<uint2*>(&sA_lo[off]) = lo;
            split4(bv[i], hi, lo);
            *reinterpret_cast<uint2*>(&sB_hi[off]) = hi;
            *reinterpret_cast<uint2*>(&sB_lo[off]) = lo;
        }
        __syncthreads();

        // ---- 3 passes: hi*hi, lo*hi, hi*lo
#pragma unroll
        for (int pass = 0; pass < 3; pass++) {
            const __nv_bfloat16* Ap = (pass == 1) ? sA_lo : sA_hi;
            const __nv_bfloat16* Bp = (pass == 2) ? sB_lo : sB_hi;
#pragma unroll
            for (int ks = 0; ks < 2; ks++) {
                uint32_t a[2][4];
#pragma unroll
                for (int mi = 0; mi < 2; mi++) {
                    uint32_t addr = smem_u32(
                        &Ap[(wm0 + mi * 16 + (lane & 15)) * LDS +
                            ks * 16 + (lane >> 4) * 8]);
                    ldmatrix_x4(a[mi][0], a[mi][1], a[mi][2], a[mi][3], addr);
                }
                uint32_t b[4][4];
#pragma unroll
                for (int np = 0; np < 4; np++) {
                    uint32_t addr = smem_u32(
                        &Bp[(wn0 + np * 16 + ((lane >> 4) << 3) + (lane & 7)) * LDS +
                            ks * 16 + (((lane >> 3) & 1) << 3)]);
                    ldmatrix_x4(b[np][0], b[np][1], b[np][2], b[np][3], addr);
                }
#pragma unroll
                for (int mi = 0; mi < 2; mi++)
#pragma unroll
                    for (int ni = 0; ni < 8; ni++) {
                        int np = ni >> 1, h = (ni & 1) * 2;
                        mma_bf16(acc[mi][ni],
                                 a[mi][0], a[mi][1], a[mi][2], a[mi][3],
                                 b[np][h], b[np][h + 1]);
                    }
            }
        }
    }

    // ---- Epilogue: bias + ReLU, float2 stores
    const int g = lane >> 2;
    const int c = lane & 3;
#pragma unroll
    for (int mi = 0; mi < 2; mi++) {
        const int row0 = m0 + wm0 + mi * 16 + g;
        const int row1 = row0 + 8;
#pragma unroll
        for (int ni = 0; ni < 8; ni++) {
            const int col = base + n0 + wn0 + ni * 8 + 2 * c;
            const float bb0 = b1[col], bb1 = b1[col + 1];
            float2 v0, v1;
            v0.x = fmaxf(acc[mi][ni][0] + bb0, 0.0f);
            v0.y = fmaxf(acc[mi][ni][1] + bb1, 0.0f);
            v1.x = fmaxf(acc[mi][ni][2] + bb0, 0.0f);
            v1.y = fmaxf(acc[mi][ni][3] + bb1, 0.0f);
            *reinterpret_cast<float2*>(&g_h1[(size_t)row0 * DIM + col]) = v0;
            *reinterpret_cast<float2*>(&g_h1[(size_t)row1 * DIM + col]) = v1;
        }
    }
}

// ---------------------------------------------------------------------------
// FUSED layers 2+3 (unchanged): h2 lives only in shared memory.
// ---------------------------------------------------------------------------
#define FB_R    4
#define FB_BCNT 16

__global__ void __launch_bounds__(512) fused23_kernel(
    const float* __restrict__ b2,
    const float* __restrict__ b3,
    float* __restrict__ out)
{
    const int cx   = blockIdx.x;
    const int tid  = threadIdx.x;
    const int c    = tid & 63;
    const int gq   = tid >> 6;
    const int ccol = cx * 64 + c;

    __shared__ float h1s[FB_R][NBLK * 64];
    __shared__ float h2s[FB_R][NBLK * 64];

    float w2[2][NBLK], w3[2][NBLK], bv2[2], bv3[2];
#pragma unroll
    for (int u = 0; u < 2; u++) {
        int oy = gq * 2 + u;
        int o  = oy * SEC + ccol;
        bv2[u] = b2[o];
        bv3[u] = b3[o];
#pragma unroll
        for (int k = 0; k < NBLK; k++) {
            w2[u][k] = g_w2ct[k * DIM + o];
            w3[u][k] = g_w3ct[k * DIM + o];
        }
    }

    const int b0 = blockIdx.y * FB_BCNT;

    for (int s = 0; s < FB_BCNT; s += FB_R) {
#pragma unroll
        for (int l = 0; l < 2; l++) {
            int t  = tid + 512 * l;
            int r  = t >> 8;
            int q  = t & 255;
            int k  = q >> 4;
            int cc = (q & 15) * 4;
            float4 v = *reinterpret_cast<const float4*>(
                &g_h1[(size_t)(b0 + s + r) * DIM + k * SEC + cx * 64 + cc]);
            *reinterpret_cast<float4*>(&h1s[r][k * 64 + cc]) = v;
        }
        __syncthreads();

#pragma unroll
        for (int r = 0; r < FB_R; r++) {
            float iv[NBLK];
#pragma unroll
            for (int k = 0; k < NBLK; k++) iv[k] = h1s[r][k * 64 + c];
#pragma unroll
            for (int u = 0; u < 2; u++) {
                float acc = bv2[u];
#pragma unroll
                for (int k = 0; k < NBLK; k++)
                    acc = fmaf(w2[u][k], iv[k], acc);
                h2s[r][(gq * 2 + u) * 64 + c] = fmaxf(acc, 0.0f);
            }
        }
        __syncthreads();

#pragma unroll
        for (int r = 0; r < FB_R; r++) {
            float hv[NBLK];
#pragma unroll
            for (int k = 0; k < NBLK; k++) hv[k] = h2s[r][k * 64 + c];
#pragma unroll
            for (int u = 0; u < 2; u++) {
                float acc = bv3[u];
#pragma unroll
                for (int k = 0; k < NBLK; k++)
                    acc = fmaf(w3[u][k], hv[k], acc);
                out[(size_t)(b0 + s + r) * DIM + (gq * 2 + u) * SEC + ccol] = acc;
            }
        }
        __syncthreads();
    }
}

// ---------------------------------------------------------------------------
// Launch. Inputs (metadata order): x, W1, b1, W2, b2, W3, b3, m1, m2, m3
// ---------------------------------------------------------------------------
extern "C" void kernel_launch(void* const* d_in, const int* in_sizes, int n_in,
                              void* d_out, int out_size)
{
    const float* x  = (const float*)d_in[0];
    const float* W1 = (const float*)d_in[1];
    const float* b1 = (const float*)d_in[2];
    const float* W2 = (const float*)d_in[3];
    const float* b2 = (const float*)d_in[4];
    const float* W3 = (const float*)d_in[5];
    const float* b3 = (const float*)d_in[6];
    float* out = (float*)d_out;
    (void)in_sizes; (void)n_in; (void)out_size;

    // 1) Pack compact sparse weight tables
    pack_kernel<<<(NBLK * DIM + 255) / 256, 256>>>(W2, W3);

    // 2) Layer 1 on tensor cores (mma.sync bf16, bf16x3 split)
    layer1_mma_kernel<<<dim3(BATCH / 128, 2, NBLK), 256>>>(x, W1, b1);

    // 3) Layers 2+3 fused
    fused23_kernel<<<dim3(4, BATCH / FB_BCNT), 512>>>(b2, b3, out);
}